// round 1
// baseline (speedup 1.0000x reference)
#include <cuda_runtime.h>
#include <math.h>

#define NN 8192
#define F  256
#define ALPHA_C 0.2f

// ---------------- scratch (device globals; no allocation allowed) ----------------
__device__ float g_Wh[NN * F];     // 8 MB, L2-resident
__device__ float g_ssrc[NN];
__device__ float g_sdst[NN];
__device__ float g_E0[NN];         // exp(sdst_j)
__device__ float g_E1[NN];         // exp(ALPHA*sdst_j)
__device__ float g_c0[NN];         // exp(ssrc_i - m_i)
__device__ float g_c1[NN];         // exp(ALPHA*ssrc_i - m_i)

// ---------------- K1: Wh = X @ W^T  (8192x256 @ 256x256) ----------------
// BM=64, BN=256(full), BK=16. 256 threads, each computes 8 rows x (4+4) cols.
__global__ void __launch_bounds__(256) k1_wh(const float* __restrict__ X,
                                             const float* __restrict__ W) {
    __shared__ float Xs[16][64];
    __shared__ float Ws[16][256];
    const int tid = threadIdx.x;
    const int i0  = blockIdx.x * 64;
    const int ty  = tid >> 5;      // 0..7
    const int tx  = tid & 31;      // 0..31
    const int r   = tid & 63;      // row within tile for loads
    const int kg  = tid >> 6;      // 0..3

    float acc[8][8];
#pragma unroll
    for (int m = 0; m < 8; m++)
#pragma unroll
        for (int n = 0; n < 8; n++) acc[m][n] = 0.f;

    for (int f0 = 0; f0 < F; f0 += 16) {
        // X tile [64 rows][16 f] stored transposed Xs[k][r]
        float4 xv = *(const float4*)&X[(i0 + r) * F + f0 + kg * 4];
        Xs[kg * 4 + 0][r] = xv.x;
        Xs[kg * 4 + 1][r] = xv.y;
        Xs[kg * 4 + 2][r] = xv.z;
        Xs[kg * 4 + 3][r] = xv.w;
        // W tile: thread tid owns output-row o=tid, loads W[o][f0..f0+15]
        const float* wp = &W[tid * F + f0];
        float4 w0 = *(const float4*)(wp + 0);
        float4 w1 = *(const float4*)(wp + 4);
        float4 w2 = *(const float4*)(wp + 8);
        float4 w3 = *(const float4*)(wp + 12);
        Ws[0][tid]  = w0.x;  Ws[1][tid]  = w0.y;  Ws[2][tid]  = w0.z;  Ws[3][tid]  = w0.w;
        Ws[4][tid]  = w1.x;  Ws[5][tid]  = w1.y;  Ws[6][tid]  = w1.z;  Ws[7][tid]  = w1.w;
        Ws[8][tid]  = w2.x;  Ws[9][tid]  = w2.y;  Ws[10][tid] = w2.z;  Ws[11][tid] = w2.w;
        Ws[12][tid] = w3.x;  Ws[13][tid] = w3.y;  Ws[14][tid] = w3.z;  Ws[15][tid] = w3.w;
        __syncthreads();
#pragma unroll
        for (int kk = 0; kk < 16; kk++) {
            float av[8], bv[8];
            *(float4*)(av + 0) = *(const float4*)&Xs[kk][ty * 8 + 0];
            *(float4*)(av + 4) = *(const float4*)&Xs[kk][ty * 8 + 4];
            *(float4*)(bv + 0) = *(const float4*)&Ws[kk][tx * 4];
            *(float4*)(bv + 4) = *(const float4*)&Ws[kk][128 + tx * 4];
#pragma unroll
            for (int m = 0; m < 8; m++)
#pragma unroll
                for (int n = 0; n < 8; n++) acc[m][n] += av[m] * bv[n];
        }
        __syncthreads();
    }
#pragma unroll
    for (int m = 0; m < 8; m++) {
        int row = i0 + ty * 8 + m;
        *(float4*)&g_Wh[row * F + tx * 4]       = make_float4(acc[m][0], acc[m][1], acc[m][2], acc[m][3]);
        *(float4*)&g_Wh[row * F + 128 + tx * 4] = make_float4(acc[m][4], acc[m][5], acc[m][6], acc[m][7]);
    }
}

// ---------------- K2: ssrc/sdst = Wh @ r_src / r_dst, exp tables ----------------
__global__ void __launch_bounds__(256) k2_scores(const float* __restrict__ r) {
    const int gwarp = (blockIdx.x * blockDim.x + threadIdx.x) >> 5;
    const int lane  = threadIdx.x & 31;
    if (gwarp >= NN) return;
    const float* row = &g_Wh[gwarp * F];
    float ss = 0.f, sd = 0.f;
#pragma unroll
    for (int q = 0; q < 8; q++) {
        int k = lane + q * 32;
        float v = row[k];
        ss += v * __ldg(&r[k]);
        sd += v * __ldg(&r[F + k]);
    }
#pragma unroll
    for (int o = 16; o > 0; o >>= 1) {
        ss += __shfl_xor_sync(0xffffffffu, ss, o);
        sd += __shfl_xor_sync(0xffffffffu, sd, o);
    }
    if (lane == 0) {
        g_ssrc[gwarp] = ss;
        g_sdst[gwarp] = sd;
        g_E0[gwarp]   = expf(sd);
        g_E1[gwarp]   = expf(ALPHA_C * sd);
    }
}

// ---------------- K3: per-row masked max of sdst; c0/c1 constants ----------------
__global__ void __launch_bounds__(256) k3_rowmax(const int* __restrict__ A) {
    const int i   = blockIdx.x;
    const int tid = threadIdx.x;
    const int4* arow = (const int4*)(A + (long long)i * NN);
    float m = -INFINITY;
    for (int q = tid; q < NN / 4; q += 256) {
        int4 a = arow[q];
        int j = q * 4;
        if (a.x) m = fmaxf(m, __ldg(&g_sdst[j + 0]));
        if (a.y) m = fmaxf(m, __ldg(&g_sdst[j + 1]));
        if (a.z) m = fmaxf(m, __ldg(&g_sdst[j + 2]));
        if (a.w) m = fmaxf(m, __ldg(&g_sdst[j + 3]));
    }
    __shared__ float red[256];
    red[tid] = m;
    __syncthreads();
    for (int s = 128; s > 0; s >>= 1) {
        if (tid < s) red[tid] = fmaxf(red[tid], red[tid + s]);
        __syncthreads();
    }
    if (tid == 0) {
        float rmax = red[0];
        float si   = g_ssrc[i];
        float t    = si + rmax;
        float mi   = (t >= 0.f) ? t : ALPHA_C * t;   // lrelu monotone -> row max of e
        g_c0[i] = expf(si - mi);
        g_c1[i] = expf(ALPHA_C * si - mi);
    }
}

// ---------------- K4: fused  out = gelu( (Wattn @ Wh) / Z ) ----------------
// BM=64 rows x BN=256 cols per CTA; BK=16. w tile built on the fly from A + scalars.
__global__ void __launch_bounds__(256) k4_main(const int* __restrict__ A,
                                               float* __restrict__ out) {
    __shared__ float Whs[16][256];   // 16KB
    __shared__ float ws[16][64];     // 4KB  (w transposed: ws[k][row])
    __shared__ float sis[64], c0s[64], c1s[64];
    __shared__ float zsh[256];
    __shared__ float zinv[64];

    const int tid = threadIdx.x;
    const int i0  = blockIdx.x * 64;
    const int ty  = tid >> 5, tx = tid & 31;
    const int r   = tid & 63, kg = tid >> 6;   // w-builder mapping

    if (tid < 64) {
        sis[tid] = g_ssrc[i0 + tid];
        c0s[tid] = g_c0[i0 + tid];
        c1s[tid] = g_c1[i0 + tid];
    }
    __syncthreads();

    const float si = sis[r], c0 = c0s[r], c1 = c1s[r];
    const int*  arow = A + (long long)(i0 + r) * NN + kg * 4;

    // Wh tile loader mapping
    const int lkk = tid >> 4;          // 0..15
    const int lc  = (tid & 15) * 16;   // 0..240

    float acc[8][8];
#pragma unroll
    for (int m = 0; m < 8; m++)
#pragma unroll
        for (int n = 0; n < 8; n++) acc[m][n] = 0.f;
    float zp = 0.f;

    for (int j0 = 0; j0 < NN; j0 += 16) {
        // load Wh[j0..j0+15][0..255] into shared (L2-resident source)
        {
            const float* src = &g_Wh[(j0 + lkk) * F + lc];
            float4 v0 = *(const float4*)(src + 0);
            float4 v1 = *(const float4*)(src + 4);
            float4 v2 = *(const float4*)(src + 8);
            float4 v3 = *(const float4*)(src + 12);
            *(float4*)&Whs[lkk][lc + 0]  = v0;
            *(float4*)&Whs[lkk][lc + 4]  = v1;
            *(float4*)&Whs[lkk][lc + 8]  = v2;
            *(float4*)&Whs[lkk][lc + 12] = v3;
        }
        // build w tile: thread handles (row r, 4 consecutive j)
        {
            int4 a = *(const int4*)(arow + j0);
            int j = j0 + kg * 4;
            float t0 = si + __ldg(&g_sdst[j + 0]);
            float t1 = si + __ldg(&g_sdst[j + 1]);
            float t2 = si + __ldg(&g_sdst[j + 2]);
            float t3 = si + __ldg(&g_sdst[j + 3]);
            float w0 = (t0 >= 0.f) ? c0 * __ldg(&g_E0[j + 0]) : c1 * __ldg(&g_E1[j + 0]);
            float w1 = (t1 >= 0.f) ? c0 * __ldg(&g_E0[j + 1]) : c1 * __ldg(&g_E1[j + 1]);
            float w2 = (t2 >= 0.f) ? c0 * __ldg(&g_E0[j + 2]) : c1 * __ldg(&g_E1[j + 2]);
            float w3 = (t3 >= 0.f) ? c0 * __ldg(&g_E0[j + 3]) : c1 * __ldg(&g_E1[j + 3]);
            w0 = a.x ? w0 : 0.f;
            w1 = a.y ? w1 : 0.f;
            w2 = a.z ? w2 : 0.f;
            w3 = a.w ? w3 : 0.f;
            ws[kg * 4 + 0][r] = w0;
            ws[kg * 4 + 1][r] = w1;
            ws[kg * 4 + 2][r] = w2;
            ws[kg * 4 + 3][r] = w3;
            zp += (w0 + w1) + (w2 + w3);
        }
        __syncthreads();
#pragma unroll
        for (int kk = 0; kk < 16; kk++) {
            float av[8], bv[8];
            *(float4*)(av + 0) = *(const float4*)&ws[kk][ty * 8 + 0];
            *(float4*)(av + 4) = *(const float4*)&ws[kk][ty * 8 + 4];
            *(float4*)(bv + 0) = *(const float4*)&Whs[kk][tx * 4];
            *(float4*)(bv + 4) = *(const float4*)&Whs[kk][128 + tx * 4];
#pragma unroll
            for (int m = 0; m < 8; m++)
#pragma unroll
                for (int n = 0; n < 8; n++) acc[m][n] += av[m] * bv[n];
        }
        __syncthreads();
    }

    // reduce Z per row (4 partials per row; tid = kg*64 + r)
    zsh[tid] = zp;
    __syncthreads();
    if (tid < 64) {
        float z = ((zsh[tid] + zsh[tid + 64]) + (zsh[tid + 128] + zsh[tid + 192]));
        zinv[tid] = 1.0f / z;
    }
    __syncthreads();

    // epilogue: divide by Z, exact GELU, store
#pragma unroll
    for (int m = 0; m < 8; m++) {
        int row = i0 + ty * 8 + m;
        float zi = zinv[ty * 8 + m];
        float o[8];
#pragma unroll
        for (int n = 0; n < 8; n++) {
            float x = acc[m][n] * zi;
            o[n] = 0.5f * x * (1.0f + erff(x * 0.70710678118654752f));
        }
        *(float4*)&out[row * F + tx * 4]       = make_float4(o[0], o[1], o[2], o[3]);
        *(float4*)&out[row * F + 128 + tx * 4] = make_float4(o[4], o[5], o[6], o[7]);
    }
}

// ---------------- launch ----------------
extern "C" void kernel_launch(void* const* d_in, const int* in_sizes, int n_in,
                              void* d_out, int out_size) {
    (void)in_sizes; (void)n_in; (void)out_size;
    const float* X = (const float*)d_in[0];
    const int*   A = (const int*)d_in[1];
    const float* W = (const float*)d_in[2];
    const float* r = (const float*)d_in[3];
    float* out = (float*)d_out;

    k1_wh<<<NN / 64, 256>>>(X, W);
    k2_scores<<<(NN * 32) / 256, 256>>>(r);
    k3_rowmax<<<NN, 256>>>(A);
    k4_main<<<NN / 64, 256>>>(A, out);
}

// round 2
// speedup vs baseline: 2.2939x; 2.2939x over previous
#include <cuda_runtime.h>
#include <math.h>
#include <stdint.h>

#define NN 8192
#define F  256
#define ALPHA_C 0.2f

// ---------------- scratch ----------------
__device__ float    g_Wh[NN * F];      // exact fp32 Wh (for scores)
__device__ uint32_t g_Wh_tf[NN * F];   // tf32-rounded Wh (B operand of k4)
__device__ float    g_ssrc[NN];
__device__ float    g_sdst[NN];
__device__ float    g_E0[NN];          // exp(sdst_j)
__device__ float    g_E1[NN];          // exp(ALPHA*sdst_j)
__device__ float    g_c0[NN];          // exp(ssrc_i - m_i)
__device__ float    g_c1[NN];          // exp(ALPHA*ssrc_i - m_i)

__device__ __forceinline__ uint32_t f2tf(float x) {
    uint32_t r;
    asm("cvt.rna.tf32.f32 %0, %1;" : "=r"(r) : "f"(x));
    return r;
}

__device__ __forceinline__ void mma_tf32(float* d, const uint32_t* a, const uint32_t* b) {
    asm volatile(
        "mma.sync.aligned.m16n8k8.row.col.f32.tf32.tf32.f32 "
        "{%0,%1,%2,%3}, {%4,%5,%6,%7}, {%8,%9}, {%0,%1,%2,%3};\n"
        : "+f"(d[0]), "+f"(d[1]), "+f"(d[2]), "+f"(d[3])
        : "r"(a[0]), "r"(a[1]), "r"(a[2]), "r"(a[3]), "r"(b[0]), "r"(b[1]));
}

// ---------------- K1: Wh = X @ W^T (fp32 exact) + tf32 copy ----------------
__global__ void __launch_bounds__(256) k1_wh(const float* __restrict__ X,
                                             const float* __restrict__ W) {
    __shared__ float Xs[16][64];
    __shared__ float Ws[16][256];
    const int tid = threadIdx.x;
    const int i0  = blockIdx.x * 64;
    const int ty  = tid >> 5;
    const int tx  = tid & 31;
    const int r   = tid & 63;
    const int kg  = tid >> 6;

    float acc[8][8];
#pragma unroll
    for (int m = 0; m < 8; m++)
#pragma unroll
        for (int n = 0; n < 8; n++) acc[m][n] = 0.f;

    for (int f0 = 0; f0 < F; f0 += 16) {
        float4 xv = *(const float4*)&X[(i0 + r) * F + f0 + kg * 4];
        Xs[kg * 4 + 0][r] = xv.x;
        Xs[kg * 4 + 1][r] = xv.y;
        Xs[kg * 4 + 2][r] = xv.z;
        Xs[kg * 4 + 3][r] = xv.w;
        const float* wp = &W[tid * F + f0];
        float4 w0 = *(const float4*)(wp + 0);
        float4 w1 = *(const float4*)(wp + 4);
        float4 w2 = *(const float4*)(wp + 8);
        float4 w3 = *(const float4*)(wp + 12);
        Ws[0][tid]  = w0.x;  Ws[1][tid]  = w0.y;  Ws[2][tid]  = w0.z;  Ws[3][tid]  = w0.w;
        Ws[4][tid]  = w1.x;  Ws[5][tid]  = w1.y;  Ws[6][tid]  = w1.z;  Ws[7][tid]  = w1.w;
        Ws[8][tid]  = w2.x;  Ws[9][tid]  = w2.y;  Ws[10][tid] = w2.z;  Ws[11][tid] = w2.w;
        Ws[12][tid] = w3.x;  Ws[13][tid] = w3.y;  Ws[14][tid] = w3.z;  Ws[15][tid] = w3.w;
        __syncthreads();
#pragma unroll
        for (int kk = 0; kk < 16; kk++) {
            float av[8], bv[8];
            *(float4*)(av + 0) = *(const float4*)&Xs[kk][ty * 8 + 0];
            *(float4*)(av + 4) = *(const float4*)&Xs[kk][ty * 8 + 4];
            *(float4*)(bv + 0) = *(const float4*)&Ws[kk][tx * 4];
            *(float4*)(bv + 4) = *(const float4*)&Ws[kk][128 + tx * 4];
#pragma unroll
            for (int m = 0; m < 8; m++)
#pragma unroll
                for (int n = 0; n < 8; n++) acc[m][n] += av[m] * bv[n];
        }
        __syncthreads();
    }
#pragma unroll
    for (int m = 0; m < 8; m++) {
        int row = i0 + ty * 8 + m;
        *(float4*)&g_Wh[row * F + tx * 4]       = make_float4(acc[m][0], acc[m][1], acc[m][2], acc[m][3]);
        *(float4*)&g_Wh[row * F + 128 + tx * 4] = make_float4(acc[m][4], acc[m][5], acc[m][6], acc[m][7]);
        *(uint4*)&g_Wh_tf[row * F + tx * 4] =
            make_uint4(f2tf(acc[m][0]), f2tf(acc[m][1]), f2tf(acc[m][2]), f2tf(acc[m][3]));
        *(uint4*)&g_Wh_tf[row * F + 128 + tx * 4] =
            make_uint4(f2tf(acc[m][4]), f2tf(acc[m][5]), f2tf(acc[m][6]), f2tf(acc[m][7]));
    }
}

// ---------------- K2: scores + exp tables ----------------
__global__ void __launch_bounds__(256) k2_scores(const float* __restrict__ r) {
    const int gwarp = (blockIdx.x * blockDim.x + threadIdx.x) >> 5;
    const int lane  = threadIdx.x & 31;
    if (gwarp >= NN) return;
    const float* row = &g_Wh[gwarp * F];
    float ss = 0.f, sd = 0.f;
#pragma unroll
    for (int q = 0; q < 8; q++) {
        int k = lane + q * 32;
        float v = row[k];
        ss += v * __ldg(&r[k]);
        sd += v * __ldg(&r[F + k]);
    }
#pragma unroll
    for (int o = 16; o > 0; o >>= 1) {
        ss += __shfl_xor_sync(0xffffffffu, ss, o);
        sd += __shfl_xor_sync(0xffffffffu, sd, o);
    }
    if (lane == 0) {
        g_ssrc[gwarp] = ss;
        g_sdst[gwarp] = sd;
        g_E0[gwarp]   = expf(sd);
        g_E1[gwarp]   = expf(ALPHA_C * sd);
    }
}

// ---------------- K3: per-row masked max ----------------
__global__ void __launch_bounds__(256) k3_rowmax(const int* __restrict__ A) {
    const int i   = blockIdx.x;
    const int tid = threadIdx.x;
    const int4* arow = (const int4*)(A + (size_t)i * NN);
    float m = -INFINITY;
    for (int q = tid; q < NN / 4; q += 256) {
        int4 a = arow[q];
        int j = q * 4;
        if (a.x) m = fmaxf(m, __ldg(&g_sdst[j + 0]));
        if (a.y) m = fmaxf(m, __ldg(&g_sdst[j + 1]));
        if (a.z) m = fmaxf(m, __ldg(&g_sdst[j + 2]));
        if (a.w) m = fmaxf(m, __ldg(&g_sdst[j + 3]));
    }
    __shared__ float red[256];
    red[tid] = m;
    __syncthreads();
    for (int s = 128; s > 0; s >>= 1) {
        if (tid < s) red[tid] = fmaxf(red[tid], red[tid + s]);
        __syncthreads();
    }
    if (tid == 0) {
        float rmax = red[0];
        float si   = g_ssrc[i];
        float t    = si + rmax;
        float mi   = (t >= 0.f) ? t : ALPHA_C * t;
        g_c0[i] = expf(si - mi);
        g_c1[i] = expf(ALPHA_C * si - mi);
    }
}

// ---------------- K4: tf32 mma, fused softmax-weight build + GELU ----------------
#define BK 32
#define WHS_STRIDE 264        // 256 + 8 pad -> conflict-free B-frag reads
#define WS_STRIDE  36         // 32 + 4 pad  -> conflict-free A-frag reads
#define WHS_BUF (32 * WHS_STRIDE)
#define WS_BUF  (64 * WS_STRIDE)
#define K4_SMEM_BYTES ((2 * WHS_BUF + 2 * WS_BUF) * 4 + 256 * 4 + 64 * 4)

__global__ void __launch_bounds__(256) k4_mma(const int* __restrict__ A,
                                              float* __restrict__ out) {
    extern __shared__ uint32_t sm[];
    uint32_t* Whs = sm;                           // [2][32][264]
    uint32_t* Wsm = sm + 2 * WHS_BUF;             // [2][64][36]
    float* zsh  = (float*)(sm + 2 * WHS_BUF + 2 * WS_BUF);  // [256]
    float* zinv = zsh + 256;                      // [64]

    const int tid  = threadIdx.x;
    const int i0   = blockIdx.x * 64;
    const int lane = tid & 31, warp = tid >> 5;
    const int g = lane >> 2, t = lane & 3;
    const int wy = warp >> 2, wx = warp & 3;

    // builder mapping
    const int r  = tid & 63;
    const int kg = tid >> 6;
    const float si = g_ssrc[i0 + r];
    const float c0 = g_c0[i0 + r];
    const float c1 = g_c1[i0 + r];
    const int4* arow = (const int4*)(A + (size_t)(i0 + r) * NN);

    // Wh tile loader mapping
    const int lkk = tid >> 3;           // 0..31
    const int lnb = (tid & 7) * 4;      // 0,4,..28

    float acc[2][8][4];
#pragma unroll
    for (int m = 0; m < 2; m++)
#pragma unroll
        for (int u = 0; u < 8; u++)
#pragma unroll
            for (int q = 0; q < 4; q++) acc[m][u][q] = 0.f;
    float zp = 0.f;

    // ---- prologue: A regs + cp.async chunk 0 ----
    int4 aA0 = arow[kg * 2 + 0];
    int4 aA1 = arow[kg * 2 + 1];
    {
        const uint32_t* src = g_Wh_tf + (size_t)lkk * F + lnb;
        uint32_t dst = (uint32_t)__cvta_generic_to_shared(&Whs[lkk * WHS_STRIDE + lnb]);
#pragma unroll
        for (int q = 0; q < 8; q++)
            asm volatile("cp.async.cg.shared.global [%0], [%1], 16;\n"
                         :: "r"(dst + q * 128), "l"(src + q * 32));
        asm volatile("cp.async.commit_group;\n");
    }

    const int NCHUNK = NN / BK;   // 256
    for (int c = 0; c < NCHUNK; c++) {
        const int buf = c & 1;
        const int j0  = c * BK;

        // prefetch next A
        int4 aB0, aB1;
        if (c < NCHUNK - 1) {
            aB0 = arow[(c + 1) * 8 + kg * 2 + 0];
            aB1 = arow[(c + 1) * 8 + kg * 2 + 1];
        }

        // ---- build w tile (tf32) ----
        {
            int va[8] = {aA0.x, aA0.y, aA0.z, aA0.w, aA1.x, aA1.y, aA1.z, aA1.w};
            uint32_t wb[8];
#pragma unroll
            for (int q = 0; q < 8; q++) {
                int j = j0 + kg * 8 + q;
                float sd = __ldg(&g_sdst[j]);
                float e0 = __ldg(&g_E0[j]);
                float e1 = __ldg(&g_E1[j]);
                float tv = si + sd;
                float w  = (tv >= 0.f) ? c0 * e0 : c1 * e1;
                w = va[q] ? w : 0.f;
                uint32_t b = f2tf(w);
                wb[q] = b;
                zp += __uint_as_float(b);
            }
            uint32_t* wrow = &Wsm[buf * WS_BUF + r * WS_STRIDE + kg * 8];
            *(uint4*)&wrow[0] = make_uint4(wb[0], wb[1], wb[2], wb[3]);
            *(uint4*)&wrow[4] = make_uint4(wb[4], wb[5], wb[6], wb[7]);
        }

        asm volatile("cp.async.wait_group 0;\n");
        __syncthreads();

        // issue next Wh tile
        if (c < NCHUNK - 1) {
            const uint32_t* src = g_Wh_tf + (size_t)(j0 + BK + lkk) * F + lnb;
            uint32_t dst = (uint32_t)__cvta_generic_to_shared(
                &Whs[(buf ^ 1) * WHS_BUF + lkk * WHS_STRIDE + lnb]);
#pragma unroll
            for (int q = 0; q < 8; q++)
                asm volatile("cp.async.cg.shared.global [%0], [%1], 16;\n"
                             :: "r"(dst + q * 128), "l"(src + q * 32));
            asm volatile("cp.async.commit_group;\n");
        }

        // ---- mma ----
        const uint32_t* wsb = &Wsm[buf * WS_BUF];
        const uint32_t* whb = &Whs[buf * WHS_BUF];
#pragma unroll
        for (int ks = 0; ks < 4; ks++) {
            uint32_t af[2][4];
#pragma unroll
            for (int m = 0; m < 2; m++) {
                const uint32_t* p = &wsb[(wy * 32 + m * 16 + g) * WS_STRIDE + ks * 8 + t];
                af[m][0] = p[0];
                af[m][1] = p[8 * WS_STRIDE];
                af[m][2] = p[4];
                af[m][3] = p[8 * WS_STRIDE + 4];
            }
            uint32_t bf[8][2];
#pragma unroll
            for (int u = 0; u < 8; u++) {
                const uint32_t* p = &whb[(ks * 8 + t) * WHS_STRIDE + wx * 64 + u * 8 + g];
                bf[u][0] = p[0];
                bf[u][1] = p[4 * WHS_STRIDE];
            }
#pragma unroll
            for (int m = 0; m < 2; m++)
#pragma unroll
                for (int u = 0; u < 8; u++)
                    mma_tf32(acc[m][u], af[m], bf[u]);
        }

        aA0 = aB0;
        aA1 = aB1;
    }

    // ---- Z reduce ----
    zsh[tid] = zp;
    __syncthreads();
    if (tid < 64) {
        float z = (zsh[tid] + zsh[tid + 64]) + (zsh[tid + 128] + zsh[tid + 192]);
        zinv[tid] = 1.0f / z;
    }
    __syncthreads();

    // ---- epilogue: /Z, exact GELU, store ----
#pragma unroll
    for (int m = 0; m < 2; m++) {
        int r0  = wy * 32 + m * 16 + g;
        float zi0 = zinv[r0];
        float zi1 = zinv[r0 + 8];
#pragma unroll
        for (int u = 0; u < 8; u++) {
            int colb = wx * 64 + u * 8 + 2 * t;
            float x0 = acc[m][u][0] * zi0;
            float x1 = acc[m][u][1] * zi0;
            float x2 = acc[m][u][2] * zi1;
            float x3 = acc[m][u][3] * zi1;
            float g0 = 0.5f * x0 * (1.0f + erff(x0 * 0.70710678118654752f));
            float g1 = 0.5f * x1 * (1.0f + erff(x1 * 0.70710678118654752f));
            float g2 = 0.5f * x2 * (1.0f + erff(x2 * 0.70710678118654752f));
            float g3 = 0.5f * x3 * (1.0f + erff(x3 * 0.70710678118654752f));
            *(float2*)&out[(size_t)(i0 + r0) * F + colb]     = make_float2(g0, g1);
            *(float2*)&out[(size_t)(i0 + r0 + 8) * F + colb] = make_float2(g2, g3);
        }
    }
}

// ---------------- launch ----------------
extern "C" void kernel_launch(void* const* d_in, const int* in_sizes, int n_in,
                              void* d_out, int out_size) {
    (void)in_sizes; (void)n_in; (void)out_size;
    const float* X = (const float*)d_in[0];
    const int*   A = (const int*)d_in[1];
    const float* W = (const float*)d_in[2];
    const float* r = (const float*)d_in[3];
    float* out = (float*)d_out;

    cudaFuncSetAttribute(k4_mma, cudaFuncAttributeMaxDynamicSharedMemorySize, K4_SMEM_BYTES);

    k1_wh<<<NN / 64, 256>>>(X, W);
    k2_scores<<<(NN * 32) / 256, 256>>>(r);
    k3_rowmax<<<NN, 256>>>(A);
    k4_mma<<<NN / 64, 256, K4_SMEM_BYTES>>>(A, out);
}